// round 16
// baseline (speedup 1.0000x reference)
#include <cuda_runtime.h>
#include <cuda_bf16.h>
#include <cuda_fp16.h>
#include <cstdint>

#define NNODES 50000
#define EMAX   800000
#define INC    256
#define HC     128
#define OUTC   64
#define NHALF  25088   // 196 blocks * 128 rows

// ---------------- scratch (static __device__ — no allocations) ----------------
__device__ __half g_H1[NNODES * 2 * HC];  // seq@W1 (fp16)     [N,256]
__device__ float  g_A1[NNODES * 2 * HC];  // agg1 (pre-act)    [N,256]
__device__ __half g_H2[NNODES * HC];      // prelu(A1)@W2 fp16 [N,128]
__device__ float  g_F [NNODES * OUTC];    // seq@PA            [N,64]

// CSR build state
__device__ int   g_off[NNODES + 1];
__device__ int   g_cnt[NNODES];
__device__ int2  g_eS[EMAX];              // dst-sorted packed {src, ew-bits}
__device__ int   g_bsum[256];

// packed bf16x2 weight splits: layout [n][K/2]
__device__ uint32_t g_W1h[2*HC * INC/2], g_W1l[2*HC * INC/2];
__device__ uint32_t g_W2h[HC * 2*HC/2],  g_W2l[HC * 2*HC/2];
__device__ uint32_t g_PAh[OUTC * INC/2], g_PAl[OUTC * INC/2];
__device__ uint32_t g_PBh[OUTC * HC/2],  g_PBl[OUTC * HC/2];

// ---------------- small helpers ----------------
__device__ __forceinline__ void cp_async16(void* smem_dst, const void* gmem_src) {
    uint32_t s = (uint32_t)__cvta_generic_to_shared(smem_dst);
    asm volatile("cp.async.cg.shared.global [%0], [%1], 16;\n" :: "r"(s), "l"(gmem_src));
}
__device__ __forceinline__ void cp_async_commit() {
    asm volatile("cp.async.commit_group;\n" ::: "memory");
}
__device__ __forceinline__ void cp_async_wait0() {
    asm volatile("cp.async.wait_group 0;\n" ::: "memory");
}
__device__ __forceinline__ uint32_t pk2(float e, float o) {
    __nv_bfloat162 p = __floats2bfloat162_rn(e, o);
    return *reinterpret_cast<uint32_t*>(&p);
}
__device__ __forceinline__ void mma_bf16(float d[4],
    uint32_t a0, uint32_t a1, uint32_t a2, uint32_t a3, uint32_t b0, uint32_t b1)
{
    asm volatile(
        "mma.sync.aligned.m16n8k16.row.col.f32.bf16.bf16.f32 "
        "{%0,%1,%2,%3}, {%4,%5,%6,%7}, {%8,%9}, {%0,%1,%2,%3};\n"
        : "+f"(d[0]), "+f"(d[1]), "+f"(d[2]), "+f"(d[3])
        : "r"(a0), "r"(a1), "r"(a2), "r"(a3), "r"(b0), "r"(b1));
}

// ---------------- prep: weight splits + cnt zero ----------------
__device__ __forceinline__ void split_one(const float* __restrict__ W,
    uint32_t* __restrict__ hi, uint32_t* __restrict__ lo, int Kp, int N, int idx)
{
    int n = idx / Kp, kp = idx % Kp;
    float v0 = W[(size_t)(2 * kp) * N + n];
    float v1 = W[(size_t)(2 * kp + 1) * N + n];
    float h0 = __bfloat162float(__float2bfloat16(v0));
    float h1 = __bfloat162float(__float2bfloat16(v1));
    hi[idx] = pk2(h0, h1);
    lo[idx] = pk2(v0 - h0, v1 - h1);
}
__global__ void prep_k(const float* __restrict__ W1, uint32_t* __restrict__ W1h,
                       uint32_t* __restrict__ W1l,
                       const float* __restrict__ W2, uint32_t* __restrict__ W2h,
                       uint32_t* __restrict__ W2l,
                       int* __restrict__ cnt, int n)
{
    int idx = blockIdx.x * blockDim.x + threadIdx.x;
    const int n1 = 2*HC * INC/2;
    const int n2 = HC * 2*HC/2;
    if (idx < n) cnt[idx] = 0;
    if (idx < n1)            split_one(W1, W1h, W1l, INC/2, 2*HC, idx);
    else if (idx < n1 + n2)  split_one(W2, W2h, W2l, 2*HC/2, HC, idx - n1);
}

// ---------------- CSR build ----------------
__global__ void hist_k(const int* __restrict__ dst, int* __restrict__ cnt, int E) {
    int e = blockIdx.x * blockDim.x + threadIdx.x;
    if (e < E) atomicAdd(&cnt[dst[e]], 1);
}
__global__ void scan1_k(const int* __restrict__ cnt, int* __restrict__ off,
                        int* __restrict__ bsum, int n)
{
    __shared__ int s[256];
    int tid = threadIdx.x;
    int i = blockIdx.x * 256 + tid;
    int v = (i < n) ? cnt[i] : 0;
    s[tid] = v; __syncthreads();
    #pragma unroll
    for (int d = 1; d < 256; d <<= 1) {
        int t = (tid >= d) ? s[tid - d] : 0;
        __syncthreads();
        s[tid] += t;
        __syncthreads();
    }
    if (i < n) off[i] = s[tid] - v;
    if (tid == 255) bsum[blockIdx.x] = s[255];
}
__global__ void scan3_k(int* __restrict__ off, const int* __restrict__ bsum,
                        int* __restrict__ cnt, int n, int E, int nb)
{
    __shared__ int red[256];
    int tid = threadIdx.x;
    int v = (tid < nb && tid < (int)blockIdx.x) ? bsum[tid] : 0;
    red[tid] = v; __syncthreads();
    #pragma unroll
    for (int d = 128; d > 0; d >>= 1) {
        if (tid < d) red[tid] += red[tid + d];
        __syncthreads();
    }
    int base = red[0];
    int i = blockIdx.x * 256 + tid;
    if (i < n) {
        int o = off[i] + base;
        off[i] = o;
        cnt[i] = o;
    }
    if (blockIdx.x == 0 && tid == 0) off[n] = E;
}
__global__ void fill_k(const int* __restrict__ dst, const int* __restrict__ src,
                       const float* __restrict__ ew, int* __restrict__ cnt,
                       int2* __restrict__ eS, int E)
{
    int e = blockIdx.x * blockDim.x + threadIdx.x;
    if (e < E) {
        int p = atomicAdd(&cnt[dst[e]], 1);
        eS[p] = make_int2(src[e], __float_as_int(ew[e]));
    }
}

// ---------------- fp16 unpack-accumulate ----------------
__device__ __forceinline__ void acc8(float* acc, uint4 v, float w) {
    float2 f;
    f = __half22float2(*reinterpret_cast<__half2*>(&v.x)); acc[0] += w * f.x; acc[1] += w * f.y;
    f = __half22float2(*reinterpret_cast<__half2*>(&v.y)); acc[2] += w * f.x; acc[3] += w * f.y;
    f = __half22float2(*reinterpret_cast<__half2*>(&v.z)); acc[4] += w * f.x; acc[5] += w * f.y;
    f = __half22float2(*reinterpret_cast<__half2*>(&v.w)); acc[6] += w * f.x; acc[7] += w * f.y;
}
__device__ __forceinline__ void acc4(float* acc, uint2 v, float w) {
    float2 f;
    f = __half22float2(*reinterpret_cast<__half2*>(&v.x)); acc[0] += w * f.x; acc[1] += w * f.y;
    f = __half22float2(*reinterpret_cast<__half2*>(&v.y)); acc[2] += w * f.x; acc[3] += w * f.y;
}

// ---------------- CSR aggregation (node range [n0, n1r)) ----------------
template<int C, bool PRELU>
__global__ void __launch_bounds__(256) agg_k(
    const __half* __restrict__ h, const int2* __restrict__ eS,
    const int* __restrict__ off,
    const float* __restrict__ bias, const float* __restrict__ alpha,
    float* __restrict__ out, int n0, int n1r)
{
    int node = n0 + blockIdx.x * 8 + (threadIdx.x >> 5);
    int lane = threadIdx.x & 31;
    if (node >= n1r) return;
    int s0 = __ldg(off + node), s1 = __ldg(off + node + 1);
    constexpr int F = C / 32;
    float acc[F];
    #pragma unroll
    for (int j = 0; j < F; j += 4) {
        float4 b4 = *reinterpret_cast<const float4*>(&bias[lane * F + j]);
        acc[j] = b4.x; acc[j+1] = b4.y; acc[j+2] = b4.z; acc[j+3] = b4.w;
    }

    int e = s0;
    if constexpr (C == 256) {
        constexpr int RS = C / 8;
        const uint4* hv = reinterpret_cast<const uint4*>(h);
        for (; e + 4 <= s1; e += 4) {
            int2 ep[4]; uint4 vv[4];
            #pragma unroll
            for (int q = 0; q < 4; q++) ep[q] = __ldg(eS + e + q);
            #pragma unroll
            for (int q = 0; q < 4; q++) vv[q] = __ldg(hv + (size_t)ep[q].x * RS + lane);
            #pragma unroll
            for (int q = 0; q < 4; q++) acc8(acc, vv[q], __int_as_float(ep[q].y));
        }
        for (; e < s1; e++) {
            int2 ep = __ldg(eS + e);
            acc8(acc, __ldg(hv + (size_t)ep.x * RS + lane), __int_as_float(ep.y));
        }
    } else {
        constexpr int RS = C / 4;
        const uint2* hv = reinterpret_cast<const uint2*>(h);
        for (; e + 4 <= s1; e += 4) {
            int2 ep[4]; uint2 vv[4];
            #pragma unroll
            for (int q = 0; q < 4; q++) ep[q] = __ldg(eS + e + q);
            #pragma unroll
            for (int q = 0; q < 4; q++) vv[q] = __ldg(hv + (size_t)ep[q].x * RS + lane);
            #pragma unroll
            for (int q = 0; q < 4; q++) acc4(acc, vv[q], __int_as_float(ep[q].y));
        }
        for (; e < s1; e++) {
            int2 ep = __ldg(eS + e);
            acc4(acc, __ldg(hv + (size_t)ep.x * RS + lane), __int_as_float(ep.y));
        }
    }

    if (PRELU) {
        float al = alpha[0];
        #pragma unroll
        for (int j = 0; j < F; j++)
            acc[j] = (acc[j] >= 0.f) ? acc[j] : al * acc[j];
    }
    #pragma unroll
    for (int j = 0; j < F; j += 4)
        *reinterpret_cast<float4*>(&out[(size_t)node * C + lane * F + j]) =
            make_float4(acc[j], acc[j+1], acc[j+2], acc[j+3]);
}

// ---------------- fused fold ----------------
__global__ void __launch_bounds__(256) fold_k(
    const float* __restrict__ Wfc1, const float* __restrict__ Wfc2,
    const float* __restrict__ Wfc3, const float* __restrict__ Wfc4,
    uint32_t* __restrict__ PAh, uint32_t* __restrict__ PAl,
    uint32_t* __restrict__ PBh, uint32_t* __restrict__ PBl)
{
    __shared__ float As[16][64];
    __shared__ float Bs[16][128];
    __shared__ float Ts[64][132];

    int b = blockIdx.x;
    const float* X; const float* W3p; uint32_t *oh, *ol; int Kp, rbase;
    if (b < 4) { X = Wfc2 + b * 64 * 256;       W3p = Wfc3;             oh = PAh; ol = PAl; Kp = 128; rbase = b * 64; }
    else       { X = Wfc1 + (b - 4) * 64 * 256; W3p = Wfc3 + 256 * 128; oh = PBh; ol = PBl; Kp = 64;  rbase = (b - 4) * 64; }

    int tid = threadIdx.x, tx = tid & 15, ty = tid >> 4;

    float acc[4][8] = {};
    for (int k0 = 0; k0 < 256; k0 += 16) {
        { int r = tid >> 2, kc = (tid & 3) * 4;
          float4 v = *reinterpret_cast<const float4*>(&X[r * 256 + k0 + kc]);
          As[kc + 0][r] = v.x; As[kc + 1][r] = v.y; As[kc + 2][r] = v.z; As[kc + 3][r] = v.w; }
        #pragma unroll
        for (int l = 0; l < 2; l++) {
            int idx = tid + l * 256;
            int kk = idx >> 5, c = (idx & 31) * 4;
            *reinterpret_cast<float4*>(&Bs[kk][c]) =
                *reinterpret_cast<const float4*>(&W3p[(k0 + kk) * 128 + c]);
        }
        __syncthreads();
        #pragma unroll
        for (int kk = 0; kk < 16; kk++) {
            float a[4], bb[8];
            #pragma unroll
            for (int i = 0; i < 4; i++) a[i] = As[kk][ty * 4 + i];
            #pragma unroll
            for (int j = 0; j < 8; j++) bb[j] = Bs[kk][tx * 8 + j];
            #pragma unroll
            for (int i = 0; i < 4; i++)
                #pragma unroll
                for (int j = 0; j < 8; j++)
                    acc[i][j] += a[i] * bb[j];
        }
        __syncthreads();
    }
    #pragma unroll
    for (int i = 0; i < 4; i++)
        #pragma unroll
        for (int j = 0; j < 8; j++)
            Ts[ty * 4 + i][tx * 8 + j] = acc[i][j];
    __syncthreads();

    float p[4][4] = {};
    for (int k = 0; k < 128; k++) {
        float4 bb = *reinterpret_cast<const float4*>(&Wfc4[k * 64 + tx * 4]);
        float a0 = Ts[ty * 4 + 0][k], a1 = Ts[ty * 4 + 1][k];
        float a2 = Ts[ty * 4 + 2][k], a3 = Ts[ty * 4 + 3][k];
        p[0][0] += a0 * bb.x; p[0][1] += a0 * bb.y; p[0][2] += a0 * bb.z; p[0][3] += a0 * bb.w;
        p[1][0] += a1 * bb.x; p[1][1] += a1 * bb.y; p[1][2] += a1 * bb.z; p[1][3] += a1 * bb.w;
        p[2][0] += a2 * bb.x; p[2][1] += a2 * bb.y; p[2][2] += a2 * bb.z; p[2][3] += a2 * bb.w;
        p[3][0] += a3 * bb.x; p[3][1] += a3 * bb.y; p[3][2] += a3 * bb.z; p[3][3] += a3 * bb.w;
    }

    #pragma unroll
    for (int i2 = 0; i2 < 2; i2++) {
        int r = ty * 4 + 2 * i2;
        #pragma unroll
        for (int j = 0; j < 4; j++) {
            float v0 = p[2 * i2][j], v1 = p[2 * i2 + 1][j];
            float h0 = __bfloat162float(__float2bfloat16(v0));
            float h1 = __bfloat162float(__float2bfloat16(v1));
            int c = tx * 4 + j;
            int w = c * Kp + (rbase + r) / 2;
            oh[w] = pk2(h0, h1);
            ol[w] = pk2(v0 - h0, v1 - h1);
        }
    }
}

// ---------------- bf16-split tensor-core GEMM ----------------
#define ASTR 20
#define BSTR 20

struct SmemTC {
    __align__(16) uint32_t Ah[128 * ASTR];
    __align__(16) uint32_t Al[128 * ASTR];
    __align__(16) uint32_t B[2][2][64 * BSTR];
};

__device__ __forceinline__ void gemm_bf_seg(
    const float* __restrict__ A, const uint32_t* __restrict__ Bh,
    const uint32_t* __restrict__ Bl, int M, int K,
    int bm, int bn, int tid, SmemTC* sm, float acc[2][4][4],
    bool doPrelu, float aA)
{
    const int lane = tid & 31, warp = tid >> 5;
    const int wm = warp & 3, wn = warp >> 2;
    const int g = lane >> 2, tq = lane & 3;
    const int Kp = K >> 1;
    const int nt = K / 32;

    float4 aS[4];

    auto stageA = [&](int t) {
        #pragma unroll
        for (int l = 0; l < 4; l++) {
            int idx = tid + l * 256;
            int r = idx >> 3, q = idx & 7;
            int row = bm + r;
            float4 v = make_float4(0.f, 0.f, 0.f, 0.f);
            if (row < M)
                v = *reinterpret_cast<const float4*>(&A[(size_t)row * K + t * 32 + q * 4]);
            aS[l] = v;
        }
    };
    auto storeA = [&]() {
        #pragma unroll
        for (int l = 0; l < 4; l++) {
            int idx = tid + l * 256;
            int r = idx >> 3, q = idx & 7;
            float4 v = aS[l];
            if (doPrelu) {
                v.x = (v.x >= 0.f) ? v.x : aA * v.x;
                v.y = (v.y >= 0.f) ? v.y : aA * v.y;
                v.z = (v.z >= 0.f) ? v.z : aA * v.z;
                v.w = (v.w >= 0.f) ? v.w : aA * v.w;
            }
            float hx = __bfloat162float(__float2bfloat16(v.x));
            float hy = __bfloat162float(__float2bfloat16(v.y));
            float hz = __bfloat162float(__float2bfloat16(v.z));
            float hw = __bfloat162float(__float2bfloat16(v.w));
            uint2 hp = make_uint2(pk2(hx, hy), pk2(hz, hw));
            uint2 lp = make_uint2(pk2(v.x - hx, v.y - hy), pk2(v.z - hz, v.w - hw));
            *reinterpret_cast<uint2*>(&sm->Ah[r * ASTR + q * 2]) = hp;
            *reinterpret_cast<uint2*>(&sm->Al[r * ASTR + q * 2]) = lp;
        }
    };
    auto cpB = [&](int t, int buf) {
        int n = tid >> 2;
        int c = (tid & 3) * 4;
        const uint32_t* sh = Bh + (size_t)(bn + n) * Kp + t * 16 + c;
        const uint32_t* sl = Bl + (size_t)(bn + n) * Kp + t * 16 + c;
        cp_async16(&sm->B[buf][0][n * BSTR + c], sh);
        cp_async16(&sm->B[buf][1][n * BSTR + c], sl);
        cp_async_commit();
    };

    stageA(0);
    cpB(0, 0);
    storeA();
    cp_async_wait0();
    __syncthreads();

    int buf = 0;
    for (int t = 0; t < nt; t++) {
        bool more = (t + 1 < nt);
        if (more) { stageA(t + 1); cpB(t + 1, buf ^ 1); }

        const uint32_t* aH = sm->Ah + (wm * 32 + g) * ASTR;
        const uint32_t* aL = sm->Al + (wm * 32 + g) * ASTR;
        const uint32_t* bH = sm->B[buf][0] + (wn * 32 + g) * BSTR;
        const uint32_t* bL = sm->B[buf][1] + (wn * 32 + g) * BSTR;

        #pragma unroll
        for (int kk = 0; kk < 2; kk++) {
            int kb = kk * 8;
            uint32_t ah[2][4], alr[2][4];
            #pragma unroll
            for (int im = 0; im < 2; im++) {
                const uint32_t* pH = aH + im * 16 * ASTR;
                const uint32_t* pL = aL + im * 16 * ASTR;
                ah[im][0] = pH[kb + tq];
                ah[im][1] = pH[8 * ASTR + kb + tq];
                ah[im][2] = pH[kb + tq + 4];
                ah[im][3] = pH[8 * ASTR + kb + tq + 4];
                alr[im][0] = pL[kb + tq];
                alr[im][1] = pL[8 * ASTR + kb + tq];
                alr[im][2] = pL[kb + tq + 4];
                alr[im][3] = pL[8 * ASTR + kb + tq + 4];
            }
            uint32_t bh[4][2], blr[4][2];
            #pragma unroll
            for (int jn = 0; jn < 4; jn++) {
                const uint32_t* qH = bH + jn * 8 * BSTR;
                const uint32_t* qL = bL + jn * 8 * BSTR;
                bh[jn][0] = qH[kb + tq];
                bh[jn][1] = qH[kb + tq + 4];
                blr[jn][0] = qL[kb + tq];
                blr[jn][1] = qL[kb + tq + 4];
            }
            #pragma unroll
            for (int im = 0; im < 2; im++)
                #pragma unroll
                for (int jn = 0; jn < 4; jn++) {
                    mma_bf16(acc[im][jn], alr[im][0], alr[im][1], alr[im][2], alr[im][3],
                             bh[jn][0], bh[jn][1]);
                    mma_bf16(acc[im][jn], ah[im][0], ah[im][1], ah[im][2], ah[im][3],
                             blr[jn][0], blr[jn][1]);
                    mma_bf16(acc[im][jn], ah[im][0], ah[im][1], ah[im][2], ah[im][3],
                             bh[jn][0], bh[jn][1]);
                }
        }
        __syncthreads();
        if (more) storeA();
        cp_async_wait0();
        __syncthreads();
        buf ^= 1;
    }
}

// HOUT=true -> D is __half*; false -> float*. Cin (optional, fp32, ldD) added pre-activation.
template<bool HOUT>
__global__ void __launch_bounds__(256, 2)
gemm_bf_k(const float* __restrict__ A, const uint32_t* __restrict__ Bh,
          const uint32_t* __restrict__ Bl, int K,
          const float* __restrict__ A2, const uint32_t* __restrict__ B2h,
          const uint32_t* __restrict__ B2l, int K2,
          const float* __restrict__ Cin,
          void* __restrict__ D, int M, int ldD,
          const float* __restrict__ preluA, const float* __restrict__ alphaOut)
{
    __shared__ SmemTC sm;
    const int tid = threadIdx.x;
    const int bm = blockIdx.y * 128, bn = blockIdx.x * 64;

    float acc[2][4][4] = {};
    const float aA = preluA ? preluA[0] : 0.f;

    gemm_bf_seg(A, Bh, Bl, M, K, bm, bn, tid, &sm, acc, preluA != nullptr, aA);
    if (A2)
        gemm_bf_seg(A2, B2h, B2l, M, K2, bm, bn, tid, &sm, acc, false, 0.f);

    const int lane = tid & 31, warp = tid >> 5;
    const int wm = warp & 3, wn = warp >> 2;
    const int g = lane >> 2, tq = lane & 3;
    const float al = alphaOut ? alphaOut[0] : 0.f;

    #pragma unroll
    for (int im = 0; im < 2; im++)
        #pragma unroll
        for (int jn = 0; jn < 4; jn++) {
            int r0 = bm + wm * 32 + im * 16 + g;
            int c0 = bn + wn * 32 + jn * 8 + 2 * tq;
            float2 v0 = make_float2(acc[im][jn][0], acc[im][jn][1]);
            float2 v1 = make_float2(acc[im][jn][2], acc[im][jn][3]);
            if (Cin) {
                if (r0 < M) {
                    float2 ci = *reinterpret_cast<const float2*>(&Cin[(size_t)r0 * ldD + c0]);
                    v0.x += ci.x; v0.y += ci.y;
                }
                if (r0 + 8 < M) {
                    float2 ci = *reinterpret_cast<const float2*>(&Cin[(size_t)(r0 + 8) * ldD + c0]);
                    v1.x += ci.x; v1.y += ci.y;
                }
            }
            if (alphaOut) {
                v0.x = (v0.x >= 0.f) ? v0.x : al * v0.x;
                v0.y = (v0.y >= 0.f) ? v0.y : al * v0.y;
                v1.x = (v1.x >= 0.f) ? v1.x : al * v1.x;
                v1.y = (v1.y >= 0.f) ? v1.y : al * v1.y;
            }
            if (HOUT) {
                __half* Dh = (__half*)D;
                if (r0 < M)
                    *reinterpret_cast<__half2*>(&Dh[(size_t)r0 * ldD + c0]) = __floats2half2_rn(v0.x, v0.y);
                if (r0 + 8 < M)
                    *reinterpret_cast<__half2*>(&Dh[(size_t)(r0 + 8) * ldD + c0]) = __floats2half2_rn(v1.x, v1.y);
            } else {
                float* Df = (float*)D;
                if (r0 < M)     *reinterpret_cast<float2*>(&Df[(size_t)r0 * ldD + c0]) = v0;
                if (r0 + 8 < M) *reinterpret_cast<float2*>(&Df[(size_t)(r0 + 8) * ldD + c0]) = v1;
            }
        }
}

// ---------------- launch ----------------
extern "C" void kernel_launch(void* const* d_in, const int* in_sizes, int n_in,
                              void* d_out, int out_size)
{
    const float* seq  = (const float*)d_in[0];
    const int*   ei   = (const int*)  d_in[1];
    const float* ew   = (const float*)d_in[2];
    const float* W1   = (const float*)d_in[3];
    const float* b1   = (const float*)d_in[4];
    const float* W2   = (const float*)d_in[5];
    const float* b2   = (const float*)d_in[6];
    const float* a1   = (const float*)d_in[7];
    const float* a2   = (const float*)d_in[8];
    const float* a3   = (const float*)d_in[9];
    const float* Wfc1 = (const float*)d_in[10];
    const float* Wfc2 = (const float*)d_in[11];
    const float* Wfc3 = (const float*)d_in[12];
    const float* Wfc4 = (const float*)d_in[13];

    const int N = in_sizes[0] / INC;     // 50000
    const int E = in_sizes[2];           // 800000
    const int* src = ei;
    const int* dst = ei + E;

    __half *H1, *H2;
    float *A1, *F;
    int *off, *cnt, *bsum;
    int2 *eS;
    uint32_t *W1h, *W1l, *W2h, *W2l, *PAh, *PAl, *PBh, *PBl;
    cudaGetSymbolAddress((void**)&H1, g_H1);
    cudaGetSymbolAddress((void**)&A1, g_A1);
    cudaGetSymbolAddress((void**)&H2, g_H2);
    cudaGetSymbolAddress((void**)&F,  g_F);
    cudaGetSymbolAddress((void**)&off, g_off);
    cudaGetSymbolAddress((void**)&cnt, g_cnt);
    cudaGetSymbolAddress((void**)&eS, g_eS);
    cudaGetSymbolAddress((void**)&bsum, g_bsum);
    cudaGetSymbolAddress((void**)&W1h, g_W1h);
    cudaGetSymbolAddress((void**)&W1l, g_W1l);
    cudaGetSymbolAddress((void**)&W2h, g_W2h);
    cudaGetSymbolAddress((void**)&W2l, g_W2l);
    cudaGetSymbolAddress((void**)&PAh, g_PAh);
    cudaGetSymbolAddress((void**)&PAl, g_PAl);
    cudaGetSymbolAddress((void**)&PBh, g_PBh);
    cudaGetSymbolAddress((void**)&PBl, g_PBl);

    float* outx = (float*)d_out;                      // x:     [N,128]
    float* outf = (float*)d_out + (size_t)N * HC;     // feat1: [N,64]

    const dim3 blk(256);
    const int gy  = (N + 127) / 128;                  // 391
    const int nb  = (N + 255) / 256;                  // 196
    const int Nh  = NHALF;                            // 25088 (196 row-blocks)
    const int gy1 = Nh / 128;                         // 196
    const int gy2 = gy - gy1;                         // 195

    static cudaStream_t sB = nullptr, sC = nullptr;
    static cudaEvent_t evRoot = nullptr, evB = nullptr, evC = nullptr;
    static cudaEvent_t evG1 = nullptr, evA1h2 = nullptr, evG2 = nullptr, evA2h2 = nullptr;
    if (sB == nullptr) {
        cudaStreamCreateWithFlags(&sB, cudaStreamNonBlocking);
        cudaStreamCreateWithFlags(&sC, cudaStreamNonBlocking);
        cudaEventCreateWithFlags(&evRoot, cudaEventDisableTiming);
        cudaEventCreateWithFlags(&evB, cudaEventDisableTiming);
        cudaEventCreateWithFlags(&evC, cudaEventDisableTiming);
        cudaEventCreateWithFlags(&evG1, cudaEventDisableTiming);
        cudaEventCreateWithFlags(&evA1h2, cudaEventDisableTiming);
        cudaEventCreateWithFlags(&evG2, cudaEventDisableTiming);
        cudaEventCreateWithFlags(&evA2h2, cudaEventDisableTiming);
    }

    // ---- root: weight splits + cnt zero ----
    prep_k<<<(N + 255) / 256, blk>>>(W1, W1h, W1l, W2, W2h, W2l, cnt, N);
    cudaEventRecord(evRoot, 0);
    cudaStreamWaitEvent(sB, evRoot, 0);
    cudaStreamWaitEvent(sC, evRoot, 0);

    // ---- stream B: CSR build ----
    hist_k<<<(E + 255) / 256, blk, 0, sB>>>(dst, cnt, E);
    scan1_k<<<nb, blk, 0, sB>>>(cnt, off, bsum, N);
    scan3_k<<<nb, blk, 0, sB>>>(off, bsum, cnt, N, E, nb);
    fill_k<<<(E + 255) / 256, blk, 0, sB>>>(dst, src, ew, cnt, eS, E);
    cudaEventRecord(evB, sB);

    // ---- stream C: head fold, then F = seq@PA (off the critical path) ----
    fold_k<<<6, blk, 0, sC>>>(Wfc1, Wfc2, Wfc3, Wfc4, PAh, PAl, PBh, PBl);
    gemm_bf_k<false><<<dim3(1, gy), blk, 0, sC>>>(seq, PAh, PAl, INC,
                                                  nullptr, nullptr, nullptr, 0,
                                                  nullptr, F, N, OUTC, nullptr, nullptr);
    cudaEventRecord(evC, sC);

    // ---- capture stream: GEMM1 overlaps CSR + fold/F ----
    gemm_bf_k<true><<<dim3(4, gy), blk>>>(seq, W1h, W1l, INC,
                                          nullptr, nullptr, nullptr, 0,
                                          nullptr, H1, N, 2*HC, nullptr, nullptr);
    cudaEventRecord(evG1, 0);

    // ---- agg1 split: h1 on main, h2 on stream B (overlaps GEMM2_h1) ----
    cudaStreamWaitEvent(0, evB, 0);
    agg_k<2*HC, false><<<(Nh + 7) / 8, blk>>>(H1, eS, off, b1, nullptr, A1, 0, Nh);
    cudaStreamWaitEvent(sB, evG1, 0);
    agg_k<2*HC, false><<<(N - Nh + 7) / 8, blk, 0, sB>>>(H1, eS, off, b1, nullptr, A1, Nh, N);
    cudaEventRecord(evA1h2, sB);

    // ---- GEMM2 split: h1 needs only agg1_h1 rows ----
    gemm_bf_k<true><<<dim3(2, gy1), blk>>>(A1, W2h, W2l, 2*HC,
                                           nullptr, nullptr, nullptr, 0,
                                           nullptr, H2, Nh, HC, a1, nullptr);
    cudaStreamWaitEvent(0, evA1h2, 0);
    gemm_bf_k<true><<<dim3(2, gy2), blk>>>(A1 + (size_t)Nh * 2*HC, W2h, W2l, 2*HC,
                                           nullptr, nullptr, nullptr, 0,
                                           nullptr, H2 + (size_t)Nh * HC, N - Nh, HC, a1, nullptr);
    cudaEventRecord(evG2, 0);

    // ---- agg2 split: h1 on main, h2 on stream B (overlaps head_h1) ----
    agg_k<HC, true><<<(Nh + 7) / 8, blk>>>(H2, eS, off, b2, a2, outx, 0, Nh);
    cudaStreamWaitEvent(sB, evG2, 0);
    agg_k<HC, true><<<(N - Nh + 7) / 8, blk, 0, sB>>>(H2, eS, off, b2, a2, outx, Nh, N);
    cudaEventRecord(evA2h2, sB);

    // ---- head split: outf = prelu(outx@PB + F, a3) ----
    cudaStreamWaitEvent(0, evC, 0);
    gemm_bf_k<false><<<dim3(1, gy1), blk>>>(outx, PBh, PBl, HC,
                                            nullptr, nullptr, nullptr, 0,
                                            F, outf, Nh, OUTC, nullptr, a3);
    cudaStreamWaitEvent(0, evA2h2, 0);
    gemm_bf_k<false><<<dim3(1, gy2), blk>>>(outx + (size_t)Nh * HC, PBh, PBl, HC,
                                            nullptr, nullptr, nullptr, 0,
                                            F + (size_t)Nh * OUTC,
                                            outf + (size_t)Nh * OUTC, N - Nh, OUTC, nullptr, a3);
}